// round 1
// baseline (speedup 1.0000x reference)
#include <cuda_runtime.h>

// SimpleTTS: only the autoregressive decoder matters (encoder output unused,
// batch rows identical). Recurrence folded to h-only:
//   g_t = Wcomb @ h_{t-1} + bcomb   (t>=1),  g_0 = bih+bhh
//   Wcomb = dec_Whh + dec_Wih @ lin_W,  bcomb = bih+bhh + dec_Wih @ lin_b
// Persistent 128-CTA kernel, weights register-resident, h exchanged via L2
// with release/acquire flags. Frames computed after the fact and broadcast.

#define HID   1024
#define GATES 4096
#define MEL   80
#define NCTA  128
#define JPC   8      // h elements owned per CTA
#define NTHR  256
#define MAXT  1024

__device__ float        d_Wcomb[GATES * HID];   // 16.7 MB
__device__ float        d_bcomb[GATES];
__device__ float        d_b0[GATES];
__device__ float        d_hhist[MAXT * HID];    // 4 MB
__device__ unsigned int d_flags[NCTA];

__device__ __forceinline__ float sigf(float x) { return 1.0f / (1.0f + expf(-x)); }

__device__ __forceinline__ void fma2(unsigned long long& acc,
                                     unsigned long long a, unsigned long long b) {
    asm("fma.rn.f32x2 %0, %1, %2, %0;" : "+l"(acc) : "l"(a), "l"(b));
}
__device__ __forceinline__ float2 unpack2(unsigned long long v) {
    float2 r;
    asm("mov.b64 {%0,%1}, %2;" : "=f"(r.x), "=f"(r.y) : "l"(v));
    return r;
}

// ---------------------------------------------------------------------------
// Prep 1: bcomb/b0 + zero flags
// ---------------------------------------------------------------------------
__global__ void prep_bias(const float* __restrict__ Wih,
                          const float* __restrict__ bih,
                          const float* __restrict__ bhh,
                          const float* __restrict__ linb) {
    int g = blockIdx.x * blockDim.x + threadIdx.x;
    if (g < GATES) {
        float s = bih[g] + bhh[g];
        d_b0[g] = s;
        float a = 0.0f;
        #pragma unroll 8
        for (int k = 0; k < MEL; ++k) a = fmaf(Wih[g * MEL + k], linb[k], a);
        d_bcomb[g] = s + a;
    }
    if (g < NCTA) d_flags[g] = 0;
}

// ---------------------------------------------------------------------------
// Prep 2: Wcomb = Whh + Wih @ lin_W   (4096x1024, k=80)
// ---------------------------------------------------------------------------
__global__ void prep_wcomb(const float* __restrict__ Wih,
                           const float* __restrict__ Whh,
                           const float* __restrict__ linW) {
    __shared__ float wih_s[16 * MEL];
    const int r0 = blockIdx.x * 16;
    for (int i = threadIdx.x; i < 16 * MEL; i += NTHR)
        wih_s[i] = Wih[r0 * MEL + i];
    __syncthreads();
    for (int c = threadIdx.x; c < HID; c += NTHR) {
        float acc[16];
        #pragma unroll
        for (int r = 0; r < 16; ++r) acc[r] = 0.0f;
        for (int k = 0; k < MEL; ++k) {
            float lw = __ldg(linW + (size_t)k * HID + c);
            #pragma unroll
            for (int r = 0; r < 16; ++r) acc[r] = fmaf(wih_s[r * MEL + k], lw, acc[r]);
        }
        #pragma unroll
        for (int r = 0; r < 16; ++r)
            d_Wcomb[(size_t)(r0 + r) * HID + c] =
                Whh[(size_t)(r0 + r) * HID + c] + acc[r];
    }
}

// ---------------------------------------------------------------------------
// Main persistent recurrence: 128 CTAs, 1/SM, weights in registers.
// Lane l of every warp owns gate-row (gate = l>>3, jj = l&7):
//   row = gate*1024 + blockIdx.x*8 + jj
// Warp w covers columns [128w, 128w+128). Cross-warp reduce via SMEM; warp 0
// finishes gates, updates c/h for its 8 h-elements, publishes h + flag.
// ---------------------------------------------------------------------------
__global__ void __launch_bounds__(NTHR, 1) tts_main(int T) {
    __shared__ float h_s[HID];
    __shared__ float red_s[NTHR];
    const int tid  = threadIdx.x;
    const int w    = tid >> 5;
    const int l    = tid & 31;
    const int ct   = blockIdx.x;
    const int jj   = l & 7;
    const int row  = (l >> 3) * HID + ct * JPC + jj;

    // Register-resident weight slice: 128 floats packed as 64 f32x2.
    unsigned long long W2[64];
    {
        const longlong2* wg =
            (const longlong2*)(d_Wcomb + (size_t)row * HID + (w << 7));
        #pragma unroll
        for (int k = 0; k < 32; ++k) {
            longlong2 v = wg[k];
            W2[2 * k]     = (unsigned long long)v.x;
            W2[2 * k + 1] = (unsigned long long)v.y;
        }
    }
    const float bc = d_bcomb[row];
    float c = 0.0f;

    // ---- step 0: g = b0 (h = x = 0) ----
    if (w == 0) {
        float gv = d_b0[row];
        float vi = __shfl_sync(0xffffffffu, gv, jj);
        float vg = __shfl_sync(0xffffffffu, gv, jj + 16);
        float vo = __shfl_sync(0xffffffffu, gv, jj + 24);
        if (l < 8) {
            c = sigf(vi) * tanhf(vg);
            float hh = sigf(vo) * tanhf(c);
            asm volatile("st.global.cg.f32 [%0], %1;"
                         :: "l"(d_hhist + ct * JPC + l), "f"(hh) : "memory");
        }
        __syncwarp();
        if (l == 0)
            asm volatile("st.release.gpu.global.u32 [%0], %1;"
                         :: "l"(d_flags + ct), "r"(1u) : "memory");
    }

    // ---- steps 1..T-1 ----
    for (int t = 1; t < T; ++t) {
        if (tid < NCTA) {          // wait for every CTA's h[t-1]
            unsigned v;
            do {
                asm volatile("ld.acquire.gpu.global.u32 %0, [%1];"
                             : "=r"(v) : "l"(d_flags + tid) : "memory");
            } while (v < (unsigned)t);
        }
        __syncthreads();

        // stage h[t-1] into SMEM (L2-only loads)
        {
            const float4* src = (const float4*)(d_hhist + (size_t)(t - 1) * HID);
            ((float4*)h_s)[tid] = __ldcg(src + tid);
        }
        __syncthreads();

        // 128-wide packed dot with broadcast SMEM reads
        unsigned long long a0 = 0ull, a1 = 0ull;
        const longlong2* h2 = (const longlong2*)(h_s + (w << 7));
        #pragma unroll
        for (int k = 0; k < 32; ++k) {
            longlong2 hv = h2[k];
            fma2(a0, W2[2 * k],     (unsigned long long)hv.x);
            fma2(a1, W2[2 * k + 1], (unsigned long long)hv.y);
        }
        float2 p0 = unpack2(a0), p1 = unpack2(a1);
        red_s[l * 8 + w] = (p0.x + p0.y) + (p1.x + p1.y);
        __syncthreads();

        if (w == 0) {
            const float4* rr = (const float4*)(red_s + l * 8);
            float4 x0 = rr[0], x1 = rr[1];
            float gv = ((x0.x + x0.y) + (x0.z + x0.w)) +
                       ((x1.x + x1.y) + (x1.z + x1.w)) + bc;
            float vi = __shfl_sync(0xffffffffu, gv, jj);
            float vf = __shfl_sync(0xffffffffu, gv, jj + 8);
            float vg = __shfl_sync(0xffffffffu, gv, jj + 16);
            float vo = __shfl_sync(0xffffffffu, gv, jj + 24);
            if (l < 8) {
                c = sigf(vf) * c + sigf(vi) * tanhf(vg);
                float hh = sigf(vo) * tanhf(c);
                asm volatile("st.global.cg.f32 [%0], %1;"
                             :: "l"(d_hhist + (size_t)t * HID + ct * JPC + l),
                                "f"(hh) : "memory");
            }
            __syncwarp();
            if (l == 0)
                asm volatile("st.release.gpu.global.u32 [%0], %1;"
                             :: "l"(d_flags + ct), "r"((unsigned)(t + 1)) : "memory");
        }
        // No trailing barrier needed: next iteration's post-poll
        // __syncthreads() orders warp 0 against h_s/red_s reuse.
    }
}

// ---------------------------------------------------------------------------
// Finalize: frames[t] = lin_W @ h_t + lin_b, broadcast across batch.
// ---------------------------------------------------------------------------
__global__ void finalize(const float* __restrict__ linW,
                         const float* __restrict__ linb,
                         float* __restrict__ out, int T, int B) {
    const int t = blockIdx.x;
    __shared__ float fr[MEL];
    const float* h = d_hhist + (size_t)t * HID;
    const int w = threadIdx.x >> 5, l = threadIdx.x & 31;
    for (int m = w; m < MEL; m += 8) {
        const float* wrow = linW + (size_t)m * HID;
        float s = 0.0f;
        #pragma unroll 8
        for (int k = l; k < HID; k += 32) s = fmaf(h[k], wrow[k], s);
        #pragma unroll
        for (int off = 16; off; off >>= 1) s += __shfl_down_sync(0xffffffffu, s, off);
        if (l == 0) fr[m] = s + linb[m];
    }
    __syncthreads();
    for (int i = threadIdx.x; i < B * MEL; i += NTHR) {
        int b = i / MEL, m = i - b * MEL;
        out[((size_t)b * T + t) * MEL + m] = fr[m];
    }
}

// ---------------------------------------------------------------------------
extern "C" void kernel_launch(void* const* d_in, const int* in_sizes, int n_in,
                              void* d_out, int out_size) {
    if (n_in < 6) return;
    // Last six inputs are always dec_Wih, dec_Whh, dec_bih, dec_bhh, lin_W, lin_b
    const float* dec_Wih = (const float*)d_in[n_in - 6];
    const float* dec_Whh = (const float*)d_in[n_in - 5];
    const float* dec_bih = (const float*)d_in[n_in - 4];
    const float* dec_bhh = (const float*)d_in[n_in - 3];
    const float* lin_W   = (const float*)d_in[n_in - 2];
    const float* lin_b   = (const float*)d_in[n_in - 1];

    const int B = in_sizes[1];               // text_lens length == batch
    int T = out_size / (B * MEL);
    if (T > MAXT) T = MAXT;
    if (T <= 0) return;

    prep_bias <<<GATES / NTHR, NTHR>>>(dec_Wih, dec_bih, dec_bhh, lin_b);
    prep_wcomb<<<GATES / 16,   NTHR>>>(dec_Wih, dec_Whh, lin_W);
    tts_main  <<<NCTA,         NTHR>>>(T);
    finalize  <<<T,            NTHR>>>(lin_W, lin_b, (float*)d_out, T, B);
}